// round 2
// baseline (speedup 1.0000x reference)
#include <cuda_runtime.h>
#include <cstdint>

#define BG   1024
#define SEQL 256
#define CH   128
#define HD   64

// scratch: [3][BG][2 heads][L][64] fp32 = 402.6 MB
__device__ float g_scratch[3ull * BG * 2 * SEQL * HD];

__device__ __forceinline__ float tf32r(float x) {
    uint32_t u;
    asm("cvt.rna.tf32.f32 %0, %1;" : "=r"(u) : "f"(x));
    return __uint_as_float(u);
}

__device__ __forceinline__ void mma_tf32(float d[4], const float a[4], const float b[2]) {
    asm volatile(
        "mma.sync.aligned.m16n8k8.row.col.f32.tf32.tf32.f32 "
        "{%0,%1,%2,%3},{%4,%5,%6,%7},{%8,%9},{%0,%1,%2,%3};\n"
        : "+f"(d[0]), "+f"(d[1]), "+f"(d[2]), "+f"(d[3])
        : "r"(__float_as_uint(a[0])), "r"(__float_as_uint(a[1])),
          "r"(__float_as_uint(a[2])), "r"(__float_as_uint(a[3])),
          "r"(__float_as_uint(b[0])), "r"(__float_as_uint(b[1])));
}

// ============================================================================
// Kernel 1: QKV projection.  grid = 2048 CTAs = (bg, m-half). 256 threads.
// Per CTA: out[128 rows, 384 cols] = x_tile[128,128] @ W^T + b, written to
// scratch[d][bg][h][l][c].
// ============================================================================
#define XSTR 132   // 132 % 32 = 4 -> fragment lds conflict-free

__global__ __launch_bounds__(256, 1)
void qkv_kernel(const float* __restrict__ x, const float* __restrict__ W,
                const float* __restrict__ bias) {
    extern __shared__ float sm[];
    float* xs = sm;                    // [128][132]
    float* ws = sm + 128 * XSTR;       // [128][132]
    float* bs = sm + 2 * 128 * XSTR;   // [384]

    const int bid = blockIdx.x;
    const int bg  = bid >> 1;
    const int m0  = (bid & 1) * 128;
    const int tid = threadIdx.x, lane = tid & 31, wid = tid >> 5;
    const int r = lane >> 2, t = lane & 3;
    const int warp_m = wid & 3, warp_n = wid >> 2;   // 4 x 2 warp grid
    const int mbase = warp_m * 32, nbase = warp_n * 64;

    // load x tile (tf32-rounded)
    const float* xp = x + ((size_t)bg * SEQL + m0) * CH;
    for (int i = tid; i < 4096; i += 256) {
        int m = i >> 5, k4 = (i & 31) << 2;
        float4 v = *(const float4*)(xp + m * CH + k4);
        float* dp = xs + m * XSTR + k4;
        dp[0] = tf32r(v.x); dp[1] = tf32r(v.y); dp[2] = tf32r(v.z); dp[3] = tf32r(v.w);
    }
    for (int i = tid; i < 384; i += 256) bs[i] = bias[i];

    for (int d = 0; d < 3; d++) {
        if (d) __syncthreads();   // previous part's mma done reading ws
        const float* wp = W + (size_t)d * 128 * CH;
        for (int i = tid; i < 4096; i += 256) {
            int n = i >> 5, k4 = (i & 31) << 2;
            float4 v = *(const float4*)(wp + n * CH + k4);
            float* dp = ws + n * XSTR + k4;
            dp[0] = tf32r(v.x); dp[1] = tf32r(v.y); dp[2] = tf32r(v.z); dp[3] = tf32r(v.w);
        }
        __syncthreads();

        float acc[2][8][4];
        #pragma unroll
        for (int mt = 0; mt < 2; mt++)
            #pragma unroll
            for (int nt = 0; nt < 8; nt++)
                #pragma unroll
                for (int j = 0; j < 4; j++) acc[mt][nt][j] = 0.f;

        #pragma unroll 4
        for (int kb = 0; kb < 128; kb += 8) {
            float a[2][4], b[8][2];
            #pragma unroll
            for (int mt = 0; mt < 2; mt++) {
                const float* p = xs + (mbase + mt * 16 + r) * XSTR + kb + t;
                a[mt][0] = p[0];        a[mt][2] = p[4];
                a[mt][1] = p[8 * XSTR]; a[mt][3] = p[8 * XSTR + 4];
            }
            #pragma unroll
            for (int nt = 0; nt < 8; nt++) {
                const float* p = ws + (nbase + nt * 8 + r) * XSTR + kb + t;
                b[nt][0] = p[0]; b[nt][1] = p[4];
            }
            #pragma unroll
            for (int mt = 0; mt < 2; mt++)
                #pragma unroll
                for (int nt = 0; nt < 8; nt++)
                    mma_tf32(acc[mt][nt], a[mt], b[nt]);
        }

        // epilogue: +bias, direct write to scratch[d][bg][warp_n(=h)][l][c]
        float* ob = g_scratch + (((size_t)d * BG + bg) * 2 + warp_n) * (SEQL * HD)
                  + (size_t)m0 * HD;
        #pragma unroll
        for (int mt = 0; mt < 2; mt++) {
            int row0 = mbase + mt * 16 + r;
            #pragma unroll
            for (int nt = 0; nt < 8; nt++) {
                int cc = nt * 8 + 2 * t;
                float b0 = bs[d * 128 + warp_n * 64 + cc];
                float b1 = bs[d * 128 + warp_n * 64 + cc + 1];
                *(float2*)(ob + row0 * HD + cc) =
                    make_float2(acc[mt][nt][0] + b0, acc[mt][nt][1] + b1);
                *(float2*)(ob + (row0 + 8) * HD + cc) =
                    make_float2(acc[mt][nt][2] + b0, acc[mt][nt][3] + b1);
            }
        }
    }
}

// ============================================================================
// Kernel 2: attention. grid = 2048 CTAs = (bg, h). 256 threads (8 warps).
// Flash-style online softmax; q resident in smem, K/V streamed in 64-row tiles.
// Each warp owns 32 q-rows.
// ============================================================================
#define QSTR 68    // 68 % 32 = 4 -> row-major fragment lds conflict-free
#define VSTR 72    // 72 % 32 = 8 -> V B-fragment lds (t rows, r cols) conflict-free

__global__ __launch_bounds__(256, 1)
void attn_kernel(float* __restrict__ out) {
    extern __shared__ float sm[];
    float* qs = sm;                      // [256][68]
    float* ks = qs + 256 * QSTR;         // [64][68]
    float* vs = ks + 64 * QSTR;          // [64][72]
    float* ps = vs + 64 * VSTR;          // 8 warps x [32][68]

    const int bid = blockIdx.x;
    const int bg = bid >> 1, h = bid & 1;
    const int tid = threadIdx.x, lane = tid & 31, wid = tid >> 5;
    const int r = lane >> 2, t = lane & 3;

    const size_t base = ((size_t)bg * 2 + h) * (SEQL * HD);
    const float* qp = g_scratch + base;
    const float* kp = g_scratch + (size_t)BG * 2 * SEQL * HD + base;
    const float* vp = g_scratch + 2 * (size_t)BG * 2 * SEQL * HD + base;
    const float SC = 0.08838834764831845f;   // 1/sqrt(128) folded into q

    for (int i = tid; i < 4096; i += 256) {
        int l = i >> 4, c4 = (i & 15) << 2;
        float4 v = *(const float4*)(qp + l * HD + c4);
        float* dp = qs + l * QSTR + c4;
        dp[0] = tf32r(v.x * SC); dp[1] = tf32r(v.y * SC);
        dp[2] = tf32r(v.z * SC); dp[3] = tf32r(v.w * SC);
    }

    float o[2][8][4];
    #pragma unroll
    for (int mt = 0; mt < 2; mt++)
        #pragma unroll
        for (int nt = 0; nt < 8; nt++)
            #pragma unroll
            for (int j = 0; j < 4; j++) o[mt][nt][j] = 0.f;
    float mrow[2][2] = {{-1e30f, -1e30f}, {-1e30f, -1e30f}};
    float lsum[2][2] = {{0.f, 0.f}, {0.f, 0.f}};

    float* psw = ps + wid * 32 * QSTR;
    const int qrow = wid * 32;

    for (int kt = 0; kt < 4; kt++) {
        __syncthreads();   // all warps done reading ks/vs of prior tile
        for (int i = tid; i < 1024; i += 256) {
            int row = i >> 4, c4 = (i & 15) << 2;
            float4 kv = *(const float4*)(kp + (kt * 64 + row) * HD + c4);
            float4 vv = *(const float4*)(vp + (kt * 64 + row) * HD + c4);
            float* dk = ks + row * QSTR + c4;
            dk[0] = tf32r(kv.x); dk[1] = tf32r(kv.y); dk[2] = tf32r(kv.z); dk[3] = tf32r(kv.w);
            float* dv = vs + row * VSTR + c4;
            dv[0] = tf32r(vv.x); dv[1] = tf32r(vv.y); dv[2] = tf32r(vv.z); dv[3] = tf32r(vv.w);
        }
        __syncthreads();

        // ---- S = q @ k^T  (M=32, N=64 keypos, K=64 chan) ----
        float s[2][8][4];
        #pragma unroll
        for (int mt = 0; mt < 2; mt++)
            #pragma unroll
            for (int nt = 0; nt < 8; nt++)
                #pragma unroll
                for (int j = 0; j < 4; j++) s[mt][nt][j] = 0.f;

        #pragma unroll
        for (int c8 = 0; c8 < 8; c8++) {
            float a[2][4], b[8][2];
            #pragma unroll
            for (int mt = 0; mt < 2; mt++) {
                const float* p = qs + (qrow + mt * 16 + r) * QSTR + c8 * 8 + t;
                a[mt][0] = p[0];        a[mt][2] = p[4];
                a[mt][1] = p[8 * QSTR]; a[mt][3] = p[8 * QSTR + 4];
            }
            #pragma unroll
            for (int nt = 0; nt < 8; nt++) {
                const float* p = ks + (nt * 8 + r) * QSTR + c8 * 8 + t;
                b[nt][0] = p[0]; b[nt][1] = p[4];
            }
            #pragma unroll
            for (int mt = 0; mt < 2; mt++)
                #pragma unroll
                for (int nt = 0; nt < 8; nt++)
                    mma_tf32(s[mt][nt], a[mt], b[nt]);
        }

        // ---- online softmax update (rows: mt*16 + hf*8 + r) ----
        #pragma unroll
        for (int mt = 0; mt < 2; mt++)
            #pragma unroll
            for (int hf = 0; hf < 2; hf++) {
                float mx = -1e30f;
                #pragma unroll
                for (int nt = 0; nt < 8; nt++)
                    mx = fmaxf(mx, fmaxf(s[mt][nt][2 * hf], s[mt][nt][2 * hf + 1]));
                mx = fmaxf(mx, __shfl_xor_sync(0xffffffffu, mx, 1));
                mx = fmaxf(mx, __shfl_xor_sync(0xffffffffu, mx, 2));
                float mold = mrow[mt][hf];
                float mnew = fmaxf(mold, mx);
                float alpha = __expf(mold - mnew);
                float rs = 0.f;
                #pragma unroll
                for (int nt = 0; nt < 8; nt++) {
                    float p0 = __expf(s[mt][nt][2 * hf]     - mnew);
                    float p1 = __expf(s[mt][nt][2 * hf + 1] - mnew);
                    s[mt][nt][2 * hf] = p0; s[mt][nt][2 * hf + 1] = p1;
                    rs += p0 + p1;
                }
                rs += __shfl_xor_sync(0xffffffffu, rs, 1);
                rs += __shfl_xor_sync(0xffffffffu, rs, 2);
                lsum[mt][hf] = lsum[mt][hf] * alpha + rs;
                mrow[mt][hf] = mnew;
                #pragma unroll
                for (int nt = 0; nt < 8; nt++) {
                    o[mt][nt][2 * hf]     *= alpha;
                    o[mt][nt][2 * hf + 1] *= alpha;
                }
            }

        // ---- stage P into per-warp smem (tf32) ----
        __syncwarp();   // all lanes done reading psw from previous tile's O-mma
        #pragma unroll
        for (int mt = 0; mt < 2; mt++) {
            int row0 = mt * 16 + r;
            #pragma unroll
            for (int nt = 0; nt < 8; nt++) {
                int cc = nt * 8 + 2 * t;
                *(float2*)(psw + row0 * QSTR + cc) =
                    make_float2(tf32r(s[mt][nt][0]), tf32r(s[mt][nt][1]));
                *(float2*)(psw + (row0 + 8) * QSTR + cc) =
                    make_float2(tf32r(s[mt][nt][2]), tf32r(s[mt][nt][3]));
            }
        }
        __syncwarp();

        // ---- O += P @ V  (M=32, N=64 headdim, K=64 keypos) ----
        #pragma unroll
        for (int k8 = 0; k8 < 8; k8++) {
            float a[2][4], b[8][2];
            #pragma unroll
            for (int mt = 0; mt < 2; mt++) {
                const float* p = psw + (mt * 16 + r) * QSTR + k8 * 8 + t;
                a[mt][0] = p[0];        a[mt][2] = p[4];
                a[mt][1] = p[8 * QSTR]; a[mt][3] = p[8 * QSTR + 4];
            }
            #pragma unroll
            for (int nt = 0; nt < 8; nt++) {
                const float* p = vs + (k8 * 8 + t) * VSTR + nt * 8 + r;
                b[nt][0] = p[0]; b[nt][1] = p[4 * VSTR];
            }
            #pragma unroll
            for (int mt = 0; mt < 2; mt++)
                #pragma unroll
                for (int nt = 0; nt < 8; nt++)
                    mma_tf32(o[mt][nt], a[mt], b[nt]);
        }
    }

    // ---- epilogue: O / l, write [b,g,l,(h c)] ----
    #pragma unroll
    for (int mt = 0; mt < 2; mt++) {
        float inv0 = 1.f / lsum[mt][0];
        float inv1 = 1.f / lsum[mt][1];
        int row0 = qrow + mt * 16 + r;
        #pragma unroll
        for (int nt = 0; nt < 8; nt++) {
            int col = h * 64 + nt * 8 + 2 * t;
            *(float2*)(out + ((size_t)bg * SEQL + row0) * CH + col) =
                make_float2(o[mt][nt][0] * inv0, o[mt][nt][1] * inv0);
            *(float2*)(out + ((size_t)bg * SEQL + row0 + 8) * CH + col) =
                make_float2(o[mt][nt][2] * inv1, o[mt][nt][3] * inv1);
        }
    }
}

extern "C" void kernel_launch(void* const* d_in, const int* in_sizes, int n_in,
                              void* d_out, int out_size) {
    const float* x    = (const float*)d_in[0];
    const float* Wqkv = (const float*)d_in[1];
    const float* bqkv = (const float*)d_in[2];
    float* out = (float*)d_out;

    const int smem1 = (2 * 128 * XSTR + 384) * 4;                         // 136,704 B
    const int smem2 = (256 * QSTR + 64 * QSTR + 64 * VSTR + 8 * 32 * QSTR) * 4; // 175,104 B
    cudaFuncSetAttribute(qkv_kernel,  cudaFuncAttributeMaxDynamicSharedMemorySize, smem1);
    cudaFuncSetAttribute(attn_kernel, cudaFuncAttributeMaxDynamicSharedMemorySize, smem2);

    qkv_kernel<<<2048, 256, smem1>>>(x, Wqkv, bqkv);
    attn_kernel<<<2048, 256, smem2>>>(out);
}

// round 3
// speedup vs baseline: 1.2489x; 1.2489x over previous
#include <cuda_runtime.h>
#include <cstdint>

#define BG   1024
#define SEQL 256
#define CH   128
#define HD   64

// scratch: [3][BG][2 heads][L][64] fp32 = 402.6 MB
__device__ float g_scratch[3ull * BG * 2 * SEQL * HD];

__device__ __forceinline__ float tf32r(float x) {
    uint32_t u;
    asm("cvt.rna.tf32.f32 %0, %1;" : "=r"(u) : "f"(x));
    return __uint_as_float(u);
}

__device__ __forceinline__ void mma_tf32(float d[4], const float a[4], const float b[2]) {
    asm volatile(
        "mma.sync.aligned.m16n8k8.row.col.f32.tf32.tf32.f32 "
        "{%0,%1,%2,%3},{%4,%5,%6,%7},{%8,%9},{%0,%1,%2,%3};\n"
        : "+f"(d[0]), "+f"(d[1]), "+f"(d[2]), "+f"(d[3])
        : "r"(__float_as_uint(a[0])), "r"(__float_as_uint(a[1])),
          "r"(__float_as_uint(a[2])), "r"(__float_as_uint(a[3])),
          "r"(__float_as_uint(b[0])), "r"(__float_as_uint(b[1])));
}

// ============================================================================
// Kernel 1: QKV projection.  grid = 2048 CTAs = (bg, m-half). 512 threads.
// 16 warps in a 4x4 grid; each warp owns a 32x32 output tile per d-part.
// ============================================================================
#define XSTR 132   // 132 % 32 = 4 -> fragment lds conflict-free

__global__ __launch_bounds__(512, 1)
void qkv_kernel(const float* __restrict__ x, const float* __restrict__ W,
                const float* __restrict__ bias) {
    extern __shared__ float sm[];
    float* xs = sm;                    // [128][132]
    float* ws = sm + 128 * XSTR;       // [128][132]
    float* bs = sm + 2 * 128 * XSTR;   // [384]

    const int bid = blockIdx.x;
    const int bg  = bid >> 1;
    const int m0  = (bid & 1) * 128;
    const int tid = threadIdx.x, lane = tid & 31, wid = tid >> 5;
    const int r = lane >> 2, t = lane & 3;
    const int warp_m = wid & 3, warp_n = wid >> 2;   // 4 x 4 warp grid
    const int mbase = warp_m * 32, nbase = warp_n * 32;

    // load x tile (tf32-rounded): 128x128 = 4096 float4
    const float* xp = x + ((size_t)bg * SEQL + m0) * CH;
    for (int i = tid; i < 4096; i += 512) {
        int m = i >> 5, k4 = (i & 31) << 2;
        float4 v = *(const float4*)(xp + m * CH + k4);
        float* dp = xs + m * XSTR + k4;
        dp[0] = tf32r(v.x); dp[1] = tf32r(v.y); dp[2] = tf32r(v.z); dp[3] = tf32r(v.w);
    }
    if (tid < 384) bs[tid] = bias[tid];

    for (int d = 0; d < 3; d++) {
        if (d) __syncthreads();   // previous part's mma done reading ws
        const float* wp = W + (size_t)d * 128 * CH;
        for (int i = tid; i < 4096; i += 512) {
            int n = i >> 5, k4 = (i & 31) << 2;
            float4 v = *(const float4*)(wp + n * CH + k4);
            float* dp = ws + n * XSTR + k4;
            dp[0] = tf32r(v.x); dp[1] = tf32r(v.y); dp[2] = tf32r(v.z); dp[3] = tf32r(v.w);
        }
        __syncthreads();

        float acc[2][4][4];
        #pragma unroll
        for (int mt = 0; mt < 2; mt++)
            #pragma unroll
            for (int nt = 0; nt < 4; nt++)
                #pragma unroll
                for (int j = 0; j < 4; j++) acc[mt][nt][j] = 0.f;

        #pragma unroll 4
        for (int kb = 0; kb < 128; kb += 8) {
            float a[2][4], b[4][2];
            #pragma unroll
            for (int mt = 0; mt < 2; mt++) {
                const float* p = xs + (mbase + mt * 16 + r) * XSTR + kb + t;
                a[mt][0] = p[0];        a[mt][2] = p[4];
                a[mt][1] = p[8 * XSTR]; a[mt][3] = p[8 * XSTR + 4];
            }
            #pragma unroll
            for (int nt = 0; nt < 4; nt++) {
                const float* p = ws + (nbase + nt * 8 + r) * XSTR + kb + t;
                b[nt][0] = p[0]; b[nt][1] = p[4];
            }
            #pragma unroll
            for (int mt = 0; mt < 2; mt++)
                #pragma unroll
                for (int nt = 0; nt < 4; nt++)
                    mma_tf32(acc[mt][nt], a[mt], b[nt]);
        }

        // epilogue: +bias, write to scratch[d][bg][h][l][c]
        const int h = warp_n >> 1;
        const int cbase = (warp_n & 1) * 32;
        float* ob = g_scratch + (((size_t)d * BG + bg) * 2 + h) * (SEQL * HD)
                  + (size_t)m0 * HD;
        #pragma unroll
        for (int mt = 0; mt < 2; mt++) {
            int row0 = mbase + mt * 16 + r;
            #pragma unroll
            for (int nt = 0; nt < 4; nt++) {
                int cc = cbase + nt * 8 + 2 * t;
                float b0 = bs[d * 128 + warp_n * 32 + nt * 8 + 2 * t];
                float b1 = bs[d * 128 + warp_n * 32 + nt * 8 + 2 * t + 1];
                *(float2*)(ob + row0 * HD + cc) =
                    make_float2(acc[mt][nt][0] + b0, acc[mt][nt][1] + b1);
                *(float2*)(ob + (row0 + 8) * HD + cc) =
                    make_float2(acc[mt][nt][2] + b0, acc[mt][nt][3] + b1);
            }
        }
    }
}

// ============================================================================
// Kernel 2: attention. grid = 2048 CTAs = (bg, h). 512 threads (16 warps).
// Flash-style online softmax; each warp owns 16 q-rows. P never touches smem:
// S accumulator fragments are transformed to PV A-fragments via shuffles.
// ============================================================================
#define QSTR 68    // 68 % 32 = 4 -> row-major fragment lds conflict-free
#define VSTR 72    // 72 % 32 = 8 -> V B-fragment lds (t rows, r cols) conflict-free

__global__ __launch_bounds__(512, 1)
void attn_kernel(float* __restrict__ out) {
    extern __shared__ float sm[];
    float* qs = sm;                      // [256][68]
    float* ks = qs + 256 * QSTR;         // [64][68]
    float* vs = ks + 64 * QSTR;          // [64][72]

    const int bid = blockIdx.x;
    const int bg = bid >> 1, h = bid & 1;
    const int tid = threadIdx.x, lane = tid & 31, wid = tid >> 5;
    const int r = lane >> 2, t = lane & 3;
    const int qrow = wid * 16;

    const size_t base = ((size_t)bg * 2 + h) * (SEQL * HD);
    const float* qp = g_scratch + base;
    const float* kp = g_scratch + (size_t)BG * 2 * SEQL * HD + base;
    const float* vp = g_scratch + 2 * (size_t)BG * 2 * SEQL * HD + base;
    const float SC = 0.08838834764831845f;   // 1/sqrt(128) folded into q

    // load q: 256x64 = 4096 float4
    for (int i = tid; i < 4096; i += 512) {
        int l = i >> 4, c4 = (i & 15) << 2;
        float4 v = *(const float4*)(qp + l * HD + c4);
        float* dp = qs + l * QSTR + c4;
        dp[0] = tf32r(v.x * SC); dp[1] = tf32r(v.y * SC);
        dp[2] = tf32r(v.z * SC); dp[3] = tf32r(v.w * SC);
    }

    float o[8][4];
    #pragma unroll
    for (int nt = 0; nt < 8; nt++)
        #pragma unroll
        for (int j = 0; j < 4; j++) o[nt][j] = 0.f;
    float mrow[2] = {-1e30f, -1e30f};
    float lsum[2] = {0.f, 0.f};

    const int src0 = (lane & 28) | (t >> 1);   // r*4 + t/2
    const int src1 = src0 + 2;
    const bool odd = (t & 1);

    for (int kt = 0; kt < 4; kt++) {
        __syncthreads();   // all warps done reading ks/vs of prior tile
        for (int i = tid; i < 1024; i += 512) {
            int row = i >> 4, c4 = (i & 15) << 2;
            float4 kv = *(const float4*)(kp + (kt * 64 + row) * HD + c4);
            float4 vv = *(const float4*)(vp + (kt * 64 + row) * HD + c4);
            float* dk = ks + row * QSTR + c4;
            dk[0] = tf32r(kv.x); dk[1] = tf32r(kv.y); dk[2] = tf32r(kv.z); dk[3] = tf32r(kv.w);
            float* dv = vs + row * VSTR + c4;
            dv[0] = tf32r(vv.x); dv[1] = tf32r(vv.y); dv[2] = tf32r(vv.z); dv[3] = tf32r(vv.w);
        }
        __syncthreads();

        // ---- S = q @ k^T  (M=16, N=64 keypos, K=64 chan) ----
        float s[8][4];
        #pragma unroll
        for (int nt = 0; nt < 8; nt++)
            #pragma unroll
            for (int j = 0; j < 4; j++) s[nt][j] = 0.f;

        #pragma unroll
        for (int c8 = 0; c8 < 8; c8++) {
            float a[4], b[8][2];
            {
                const float* p = qs + (qrow + r) * QSTR + c8 * 8 + t;
                a[0] = p[0];        a[2] = p[4];
                a[1] = p[8 * QSTR]; a[3] = p[8 * QSTR + 4];
            }
            #pragma unroll
            for (int nt = 0; nt < 8; nt++) {
                const float* p = ks + (nt * 8 + r) * QSTR + c8 * 8 + t;
                b[nt][0] = p[0]; b[nt][1] = p[4];
            }
            #pragma unroll
            for (int nt = 0; nt < 8; nt++)
                mma_tf32(s[nt], a, b[nt]);
        }

        // ---- online softmax (group g=0: rows r; g=1: rows r+8) ----
        #pragma unroll
        for (int g = 0; g < 2; g++) {
            float mx = -1e30f;
            #pragma unroll
            for (int nt = 0; nt < 8; nt++)
                mx = fmaxf(mx, fmaxf(s[nt][2 * g], s[nt][2 * g + 1]));
            mx = fmaxf(mx, __shfl_xor_sync(0xffffffffu, mx, 1));
            mx = fmaxf(mx, __shfl_xor_sync(0xffffffffu, mx, 2));
            float mold = mrow[g];
            float mnew = fmaxf(mold, mx);
            float alpha = __expf(mold - mnew);
            float rs = 0.f;
            #pragma unroll
            for (int nt = 0; nt < 8; nt++) {
                float p0 = __expf(s[nt][2 * g]     - mnew);
                float p1 = __expf(s[nt][2 * g + 1] - mnew);
                s[nt][2 * g] = p0; s[nt][2 * g + 1] = p1;
                rs += p0 + p1;
            }
            rs += __shfl_xor_sync(0xffffffffu, rs, 1);
            rs += __shfl_xor_sync(0xffffffffu, rs, 2);
            lsum[g] = lsum[g] * alpha + rs;
            mrow[g] = mnew;
            #pragma unroll
            for (int nt = 0; nt < 8; nt++) {
                o[nt][2 * g]     *= alpha;
                o[nt][2 * g + 1] *= alpha;
            }
        }

        // ---- O += P @ V (M=16, N=64 headdim, K=64 keypos) ----
        // A-fragment for k-group kg is s[kg] (C-layout) transformed via shuffles:
        //   a0 = P(r,   kg*8+t)   a2 = P(r,   kg*8+t+4)
        //   a1 = P(r+8, kg*8+t)   a3 = P(r+8, kg*8+t+4)
        #pragma unroll
        for (int kg = 0; kg < 8; kg++) {
            float p00 = __shfl_sync(0xffffffffu, s[kg][0], src0);
            float p01 = __shfl_sync(0xffffffffu, s[kg][1], src0);
            float p02 = __shfl_sync(0xffffffffu, s[kg][2], src0);
            float p03 = __shfl_sync(0xffffffffu, s[kg][3], src0);
            float p10 = __shfl_sync(0xffffffffu, s[kg][0], src1);
            float p11 = __shfl_sync(0xffffffffu, s[kg][1], src1);
            float p12 = __shfl_sync(0xffffffffu, s[kg][2], src1);
            float p13 = __shfl_sync(0xffffffffu, s[kg][3], src1);
            float a[4];
            a[0] = tf32r(odd ? p01 : p00);
            a[1] = tf32r(odd ? p03 : p02);
            a[2] = tf32r(odd ? p11 : p10);
            a[3] = tf32r(odd ? p13 : p12);
            #pragma unroll
            for (int nt = 0; nt < 8; nt++) {
                float b[2];
                const float* p = vs + (kg * 8 + t) * VSTR + nt * 8 + r;
                b[0] = p[0]; b[1] = p[4 * VSTR];
                mma_tf32(o[nt], a, b);
            }
        }
    }

    // ---- epilogue: O / l, write [b,g,l,(h c)] ----
    float inv0 = 1.f / lsum[0];
    float inv1 = 1.f / lsum[1];
    int row0 = qrow + r;
    #pragma unroll
    for (int nt = 0; nt < 8; nt++) {
        int col = h * 64 + nt * 8 + 2 * t;
        *(float2*)(out + ((size_t)bg * SEQL + row0) * CH + col) =
            make_float2(o[nt][0] * inv0, o[nt][1] * inv0);
        *(float2*)(out + ((size_t)bg * SEQL + row0 + 8) * CH + col) =
            make_float2(o[nt][2] * inv1, o[nt][3] * inv1);
    }
}

extern "C" void kernel_launch(void* const* d_in, const int* in_sizes, int n_in,
                              void* d_out, int out_size) {
    const float* x    = (const float*)d_in[0];
    const float* Wqkv = (const float*)d_in[1];
    const float* bqkv = (const float*)d_in[2];
    float* out = (float*)d_out;

    const int smem1 = (2 * 128 * XSTR + 384) * 4;                    // 136,704 B
    const int smem2 = (256 * QSTR + 64 * QSTR + 64 * VSTR) * 4;      // 105,472 B
    cudaFuncSetAttribute(qkv_kernel,  cudaFuncAttributeMaxDynamicSharedMemorySize, smem1);
    cudaFuncSetAttribute(attn_kernel, cudaFuncAttributeMaxDynamicSharedMemorySize, smem2);

    qkv_kernel<<<2048, 512, smem1>>>(x, Wqkv, bqkv);
    attn_kernel<<<2048, 512, smem2>>>(out);
}

// round 5
// speedup vs baseline: 1.3275x; 1.0629x over previous
#include <cuda_runtime.h>
#include <cstdint>

#define BG   1024
#define SEQL 256
#define CH   128
#define HD   64

// scratch: [3][BG][2 heads][L][64] fp32 = 402.6 MB (values tf32-rounded, q pre-scaled)
__device__ float g_scratch[3ull * BG * 2 * SEQL * HD];

__device__ __forceinline__ float tf32r(float x) {
    uint32_t u;
    asm("cvt.rna.tf32.f32 %0, %1;" : "=r"(u) : "f"(x));
    return __uint_as_float(u);
}

__device__ __forceinline__ void mma_tf32(float d[4], const float a[4], const float b[2]) {
    asm volatile(
        "mma.sync.aligned.m16n8k8.row.col.f32.tf32.tf32.f32 "
        "{%0,%1,%2,%3},{%4,%5,%6,%7},{%8,%9},{%0,%1,%2,%3};\n"
        : "+f"(d[0]), "+f"(d[1]), "+f"(d[2]), "+f"(d[3])
        : "r"(__float_as_uint(a[0])), "r"(__float_as_uint(a[1])),
          "r"(__float_as_uint(a[2])), "r"(__float_as_uint(a[3])),
          "r"(__float_as_uint(b[0])), "r"(__float_as_uint(b[1])));
}

// ============================================================================
// Kernel 1: QKV projection.  grid = 2048 CTAs = (bg, m-half). 512 threads.
// Fragment-packed smem (within each 8-float k-group, pos = 2*(k&3) + ((k>>2)&1))
// so each fragment load is one LDS.64. Row stride 136 (== 8 mod 32): conflict-free.
// W parts register-prefetched. Epilogue writes tf32-rounded (+scale folded into q).
// ============================================================================
#define XSTR 136

__global__ __launch_bounds__(512, 1)
void qkv_kernel(const float* __restrict__ x, const float* __restrict__ W,
                const float* __restrict__ bias) {
    extern __shared__ float sm[];
    float* xs = sm;                    // [128][136] packed
    float* ws = sm + 128 * XSTR;       // [128][136] packed
    float* bs = sm + 2 * 128 * XSTR;   // [384]

    const int bid = blockIdx.x;
    const int bg  = bid >> 1;
    const int m0  = (bid & 1) * 128;
    const int tid = threadIdx.x, lane = tid & 31, wid = tid >> 5;
    const int r = lane >> 2, t = lane & 3;
    const int warp_m = wid & 3, warp_n = wid >> 2;   // 4 x 4 warp grid
    const int mbase = warp_m * 32, nbase = warp_n * 32;

    float4 wreg[8];

    auto ldgW = [&](int d) {
        const float* wp = W + (size_t)d * 128 * CH;
        #pragma unroll
        for (int it = 0; it < 8; it++) {
            int i = tid + it * 512;
            int n = i >> 5, k4 = (i & 31) << 2;
            wreg[it] = *(const float4*)(wp + n * CH + k4);
        }
    };
    auto stsW = [&]() {
        #pragma unroll
        for (int it = 0; it < 8; it++) {
            int i = tid + it * 512;
            int n = i >> 5, k4 = (i & 31) << 2;
            float* dp = ws + n * XSTR + (k4 >> 3) * 8 + ((k4 >> 2) & 1);
            dp[0] = tf32r(wreg[it].x); dp[2] = tf32r(wreg[it].y);
            dp[4] = tf32r(wreg[it].z); dp[6] = tf32r(wreg[it].w);
        }
    };

    ldgW(0);

    // x tile: packed + tf32-rounded
    const float* xp = x + ((size_t)bg * SEQL + m0) * CH;
    for (int i = tid; i < 4096; i += 512) {
        int m = i >> 5, k4 = (i & 31) << 2;
        float4 v = *(const float4*)(xp + m * CH + k4);
        float* dp = xs + m * XSTR + (k4 >> 3) * 8 + ((k4 >> 2) & 1);
        dp[0] = tf32r(v.x); dp[2] = tf32r(v.y); dp[4] = tf32r(v.z); dp[6] = tf32r(v.w);
    }
    if (tid < 384) bs[tid] = bias[tid];
    stsW();
    __syncthreads();

    for (int d = 0; d < 3; d++) {
        if (d < 2) ldgW(d + 1);

        float acc[2][4][4];
        #pragma unroll
        for (int mt = 0; mt < 2; mt++)
            #pragma unroll
            for (int nt = 0; nt < 4; nt++)
                #pragma unroll
                for (int j = 0; j < 4; j++) acc[mt][nt][j] = 0.f;

        #pragma unroll 4
        for (int c8 = 0; c8 < 16; c8++) {
            float2 a02[2], a13[2], bb[4];
            #pragma unroll
            for (int mt = 0; mt < 2; mt++) {
                const float* p = xs + (mbase + mt * 16 + r) * XSTR + c8 * 8 + 2 * t;
                a02[mt] = *(const float2*)p;
                a13[mt] = *(const float2*)(p + 8 * XSTR);
            }
            #pragma unroll
            for (int nt = 0; nt < 4; nt++)
                bb[nt] = *(const float2*)(ws + (nbase + nt * 8 + r) * XSTR + c8 * 8 + 2 * t);
            #pragma unroll
            for (int mt = 0; mt < 2; mt++) {
                float a[4] = {a02[mt].x, a13[mt].x, a02[mt].y, a13[mt].y};
                #pragma unroll
                for (int nt = 0; nt < 4; nt++) {
                    float b[2] = {bb[nt].x, bb[nt].y};
                    mma_tf32(acc[mt][nt], a, b);
                }
            }
        }

        if (d < 2) { __syncthreads(); stsW(); }

        // epilogue: +bias, tf32-round, fold 1/sqrt(128) into q (d==0)
        const float scale = (d == 0) ? 0.08838834764831845f : 1.f;
        const int h = warp_n >> 1;
        const int cbase = (warp_n & 1) * 32;
        float* ob = g_scratch + (((size_t)d * BG + bg) * 2 + h) * (SEQL * HD)
                  + (size_t)m0 * HD;
        #pragma unroll
        for (int mt = 0; mt < 2; mt++) {
            int row0 = mbase + mt * 16 + r;
            #pragma unroll
            for (int nt = 0; nt < 4; nt++) {
                int cc = cbase + nt * 8 + 2 * t;
                float b0 = bs[d * 128 + warp_n * 32 + nt * 8 + 2 * t];
                float b1 = bs[d * 128 + warp_n * 32 + nt * 8 + 2 * t + 1];
                *(float2*)(ob + row0 * HD + cc) =
                    make_float2(tf32r((acc[mt][nt][0] + b0) * scale),
                                tf32r((acc[mt][nt][1] + b1) * scale));
                *(float2*)(ob + (row0 + 8) * HD + cc) =
                    make_float2(tf32r((acc[mt][nt][2] + b0) * scale),
                                tf32r((acc[mt][nt][3] + b1) * scale));
            }
        }
        if (d < 2) __syncthreads();
    }
}

// ============================================================================
// Kernel 2: attention. grid = 2048 CTAs = (bg, h). 512 threads (16 warps).
// Scratch values are tf32-clean & q pre-scaled -> loads are pure permute-copies.
// K prefetched before S-mma, V prefetched after softmax (limits live regs).
// Packed layouts -> LDS.64 fragment loads, bank-conflict-free.
// ============================================================================
#define QSTR 72    // 72 % 32 = 8
#define KSTR 72
#define VSTR 136   // V pair-packed: row kg*4+t holds {V[kg*8+t][n], V[kg*8+t+4][n]} at cols 2n,2n+1

__global__ __launch_bounds__(512, 1)
void attn_kernel(float* __restrict__ out) {
    extern __shared__ float sm[];
    float* qs = sm;                      // [256][72] packed
    float* ks = qs + 256 * QSTR;         // [64][72]  packed
    float* vs = ks + 64 * KSTR;          // [32][136] pair-packed

    const int bid = blockIdx.x;
    const int bg = bid >> 1, h = bid & 1;
    const int tid = threadIdx.x, lane = tid & 31, wid = tid >> 5;
    const int r = lane >> 2, t = lane & 3;
    const int qrow = wid * 16;

    const size_t base = ((size_t)bg * 2 + h) * (SEQL * HD);
    const float* qp = g_scratch + base;
    const float* kp = g_scratch + (size_t)BG * 2 * SEQL * HD + base;
    const float* vp = g_scratch + 2 * (size_t)BG * 2 * SEQL * HD + base;

    const int ldrow0 = tid >> 4,         ldc4_0 = (tid & 15) << 2;
    const int ldrow1 = (tid + 512) >> 4, ldc4_1 = ldc4_0;   // (tid+512)&15 == tid&15

    float4 kreg[2], vreg[2];
    auto ldgK = [&](int kt) {
        kreg[0] = *(const float4*)(kp + (kt * 64 + ldrow0) * HD + ldc4_0);
        kreg[1] = *(const float4*)(kp + (kt * 64 + ldrow1) * HD + ldc4_1);
    };
    auto ldgV = [&](int kt) {
        vreg[0] = *(const float4*)(vp + (kt * 64 + ldrow0) * HD + ldc4_0);
        vreg[1] = *(const float4*)(vp + (kt * 64 + ldrow1) * HD + ldc4_1);
    };
    auto stsKV = [&]() {
        #pragma unroll
        for (int it = 0; it < 2; it++) {
            int row = it ? ldrow1 : ldrow0;
            int c4  = it ? ldc4_1 : ldc4_0;
            float4 kv = kreg[it], vv = vreg[it];
            float* dk = ks + row * KSTR + (c4 >> 3) * 8 + ((c4 >> 2) & 1);
            dk[0] = kv.x; dk[2] = kv.y; dk[4] = kv.z; dk[6] = kv.w;
            int kg = row >> 3, i = row & 7;
            float* dv = vs + (kg * 4 + (i & 3)) * VSTR + c4 * 2 + (i >> 2);
            dv[0] = vv.x; dv[2] = vv.y; dv[4] = vv.z; dv[6] = vv.w;
        }
    };

    ldgK(0); ldgV(0);

    // q: pure permute copy (values already tf32-rounded & scaled by qkv)
    for (int i = tid; i < 4096; i += 512) {
        int l = i >> 4, c4 = (i & 15) << 2;
        float4 v = *(const float4*)(qp + l * HD + c4);
        float* dp = qs + l * QSTR + (c4 >> 3) * 8 + ((c4 >> 2) & 1);
        dp[0] = v.x; dp[2] = v.y; dp[4] = v.z; dp[6] = v.w;
    }
    stsKV();
    __syncthreads();

    float o[8][4];
    #pragma unroll
    for (int nt = 0; nt < 8; nt++)
        #pragma unroll
        for (int j = 0; j < 4; j++) o[nt][j] = 0.f;
    float mrow[2] = {-1e30f, -1e30f};
    float lsum[2] = {0.f, 0.f};

    const int src0 = (lane & 28) | (t >> 1);   // r*4 + t/2
    const int src1 = src0 + 2;
    const bool odd = (t & 1);

    for (int kt = 0; kt < 4; kt++) {
        if (kt < 3) ldgK(kt + 1);

        // ---- S = q @ k^T  (M=16, N=64 keypos, K=64 chan) ----
        float s[8][4];
        #pragma unroll
        for (int nt = 0; nt < 8; nt++)
            #pragma unroll
            for (int j = 0; j < 4; j++) s[nt][j] = 0.f;

        #pragma unroll
        for (int c8 = 0; c8 < 8; c8++) {
            const float* pq = qs + (qrow + r) * QSTR + c8 * 8 + 2 * t;
            float2 a02 = *(const float2*)pq;
            float2 a13 = *(const float2*)(pq + 8 * QSTR);
            float a[4] = {a02.x, a13.x, a02.y, a13.y};
            #pragma unroll
            for (int nt = 0; nt < 8; nt++) {
                float2 bb = *(const float2*)(ks + (nt * 8 + r) * KSTR + c8 * 8 + 2 * t);
                float b[2] = {bb.x, bb.y};
                mma_tf32(s[nt], a, b);
            }
        }

        // ---- online softmax (group g=0: rows r; g=1: rows r+8) ----
        #pragma unroll
        for (int g = 0; g < 2; g++) {
            float mx = -1e30f;
            #pragma unroll
            for (int nt = 0; nt < 8; nt++)
                mx = fmaxf(mx, fmaxf(s[nt][2 * g], s[nt][2 * g + 1]));
            mx = fmaxf(mx, __shfl_xor_sync(0xffffffffu, mx, 1));
            mx = fmaxf(mx, __shfl_xor_sync(0xffffffffu, mx, 2));
            float mold = mrow[g];
            float mnew = fmaxf(mold, mx);
            float alpha = __expf(mold - mnew);
            float rs = 0.f;
            #pragma unroll
            for (int nt = 0; nt < 8; nt++) {
                float p0 = __expf(s[nt][2 * g]     - mnew);
                float p1 = __expf(s[nt][2 * g + 1] - mnew);
                s[nt][2 * g] = p0; s[nt][2 * g + 1] = p1;
                rs += p0 + p1;
            }
            rs += __shfl_xor_sync(0xffffffffu, rs, 1);
            rs += __shfl_xor_sync(0xffffffffu, rs, 2);
            lsum[g] = lsum[g] * alpha + rs;
            mrow[g] = mnew;
            #pragma unroll
            for (int nt = 0; nt < 8; nt++) {
                o[nt][2 * g]     *= alpha;
                o[nt][2 * g + 1] *= alpha;
            }
        }

        if (kt < 3) ldgV(kt + 1);

        // ---- O += P @ V (M=16, N=64 headdim, K=64 keypos) ----
        // A-fragment from S accumulator via shuffles:
        //   a0 = P(r, kg*8+t)  a1 = P(r+8, kg*8+t)  a2 = P(r, kg*8+t+4)  a3 = P(r+8, kg*8+t+4)
        #pragma unroll
        for (int kg = 0; kg < 8; kg++) {
            float p00 = __shfl_sync(0xffffffffu, s[kg][0], src0);
            float p01 = __shfl_sync(0xffffffffu, s[kg][1], src0);
            float p02 = __shfl_sync(0xffffffffu, s[kg][2], src0);
            float p03 = __shfl_sync(0xffffffffu, s[kg][3], src0);
            float p10 = __shfl_sync(0xffffffffu, s[kg][0], src1);
            float p11 = __shfl_sync(0xffffffffu, s[kg][1], src1);
            float p12 = __shfl_sync(0xffffffffu, s[kg][2], src1);
            float p13 = __shfl_sync(0xffffffffu, s[kg][3], src1);
            float a[4];
            a[0] = tf32r(odd ? p01 : p00);
            a[1] = tf32r(odd ? p03 : p02);
            a[2] = tf32r(odd ? p11 : p10);
            a[3] = tf32r(odd ? p13 : p12);
            const float* pv = vs + (kg * 4 + t) * VSTR;
            #pragma unroll
            for (int nt = 0; nt < 8; nt++) {
                float2 bb = *(const float2*)(pv + (nt * 8 + r) * 2);
                float b[2] = {bb.x, bb.y};
                mma_tf32(o[nt], a, b);
            }
        }

        if (kt < 3) { __syncthreads(); stsKV(); __syncthreads(); }
    }

    // ---- epilogue: O / l, write [b,g,l,(h c)] ----
    float inv0 = 1.f / lsum[0];
    float inv1 = 1.f / lsum[1];
    int row0 = qrow + r;
    #pragma unroll
    for (int nt = 0; nt < 8; nt++) {
        int col = h * 64 + nt * 8 + 2 * t;
        *(float2*)(out + ((size_t)bg * SEQL + row0) * CH + col) =
            make_float2(o[nt][0] * inv0, o[nt][1] * inv0);
        *(float2*)(out + ((size_t)bg * SEQL + row0 + 8) * CH + col) =
            make_float2(o[nt][2] * inv1, o[nt][3] * inv1);
    }
}

extern "C" void kernel_launch(void* const* d_in, const int* in_sizes, int n_in,
                              void* d_out, int out_size) {
    const float* x    = (const float*)d_in[0];
    const float* Wqkv = (const float*)d_in[1];
    const float* bqkv = (const float*)d_in[2];
    float* out = (float*)d_out;

    const int smem1 = (2 * 128 * XSTR + 384) * 4;                     // 140,800 B
    const int smem2 = (256 * QSTR + 64 * KSTR + 32 * VSTR) * 4;       // 109,568 B
    cudaFuncSetAttribute(qkv_kernel,  cudaFuncAttributeMaxDynamicSharedMemorySize, smem1);
    cudaFuncSetAttribute(attn_kernel, cudaFuncAttributeMaxDynamicSharedMemorySize, smem2);

    qkv_kernel<<<2048, 512, smem1>>>(x, Wqkv, bqkv);
    attn_kernel<<<2048, 512, smem2>>>(out);
}